// round 6
// baseline (speedup 1.0000x reference)
#include <cuda_runtime.h>
#include <stdint.h>

// Shapes (fixed by the problem)
#define BATCH 32
#define SEQ   4096
#define VOCAB 10
#define FEAT  1024
#define DIM   64

#define CHUNK   256
#define THREADS 256
#define TILE_BYTES (DIM * CHUNK * 4)   // 64 KB dynamic smem per CTA

// Precomputed projected table: P[d][v] = b[d] + sum_f fp[v][f] * W[d][f]
__device__ float g_P[DIM * VOCAB];

// ---------------------------------------------------------------------------
// Kernel 1: tiny 10x64x1024 GEMM. One warp per (d, v) pair -> 640 warps.
// ---------------------------------------------------------------------------
__global__ void compute_P_kernel(const float* __restrict__ fp,
                                 const float* __restrict__ W,
                                 const float* __restrict__ bias) {
    int w    = (blockIdx.x * blockDim.x + threadIdx.x) >> 5;
    int lane = threadIdx.x & 31;
    if (w >= DIM * VOCAB) return;
    int d = w / VOCAB;
    int v = w - d * VOCAB;

    const float4* fr = reinterpret_cast<const float4*>(fp + v * FEAT);
    const float4* wr = reinterpret_cast<const float4*>(W  + d * FEAT);

    float s = 0.f;
#pragma unroll
    for (int f = lane; f < FEAT / 4; f += 32) {
        float4 a = fr[f];
        float4 c = wr[f];
        s += a.x * c.x + a.y * c.y + a.z * c.z + a.w * c.w;
    }

#pragma unroll
    for (int o = 16; o > 0; o >>= 1)
        s += __shfl_down_sync(0xffffffffu, s, o);

    if (lane == 0)
        g_P[d * VOCAB + v] = s + bias[d];
}

// ---------------------------------------------------------------------------
// Kernel 2: gather into an smem tile, drain via TMA bulk stores.
// Tile layout: tile[d][0..255] (1 KB per d-row, contiguous).
// Gather: thread owns float4 slot lq (tid&63) over 16 d-rows -> 64 LDS + 16
// STS.128, all conflict-free. Then 64 threads each issue ONE 1 KB
// cp.async.bulk (smem row -> global row) — the 33.5 MB output never touches
// the per-thread STG path.
// ---------------------------------------------------------------------------
__global__ void gather_tma_kernel(const int* __restrict__ idx,
                                  float* __restrict__ out) {
    extern __shared__ float tile[];          // DIM * CHUNK floats (64 KB)
    __shared__ float sP[DIM * VOCAB];

    const int tid = threadIdx.x;
    const int lq  = tid & 63;                // float4 slot within chunk
    const int db  = tid >> 6;                // base d-row (0..3)
    const int b   = blockIdx.y;
    const int l0  = blockIdx.x * CHUNK;

    // This thread's 4 vocab indices (coalesced 16B load, values 0..9)
    int4 iv = *reinterpret_cast<const int4*>(idx + b * SEQ + l0 + lq * 4);

    for (int i = tid; i < DIM * VOCAB; i += THREADS)
        sP[i] = g_P[i];
    __syncthreads();

#pragma unroll
    for (int k = 0; k < 16; k++) {
        const int d = db + 4 * k;
        const float* p = &sP[d * VOCAB];
        float4 r;
        r.x = p[iv.x];
        r.y = p[iv.y];
        r.z = p[iv.z];
        r.w = p[iv.w];
        *reinterpret_cast<float4*>(&tile[d * CHUNK + lq * 4]) = r;
    }
    __syncthreads();

    // Make generic-proxy smem writes visible to the async (TMA) proxy
    asm volatile("fence.proxy.async.shared::cta;" ::: "memory");

    // One 1 KB bulk store per d-row, issued by 64 threads in parallel
    if (tid < DIM) {
        uint32_t src;
        asm("{ .reg .u64 t; cvta.to.shared.u64 t, %1; cvt.u32.u64 %0, t; }"
            : "=r"(src) : "l"(tile + tid * CHUNK));
        float* dst = out + (b * DIM + tid) * SEQ + l0;
        asm volatile(
            "cp.async.bulk.global.shared::cta.bulk_group [%0], [%1], %2;"
            :: "l"(dst), "r"(src), "n"(CHUNK * 4) : "memory");
        asm volatile("cp.async.bulk.commit_group;" ::: "memory");
        asm volatile("cp.async.bulk.wait_group 0;" ::: "memory");
    }
}

// ---------------------------------------------------------------------------
// Inputs per metadata order: indices (int32), fp_table (f32), W (f32), b (f32)
// ---------------------------------------------------------------------------
extern "C" void kernel_launch(void* const* d_in, const int* in_sizes, int n_in,
                              void* d_out, int out_size) {
    const int*   idx  = (const int*)d_in[0];
    const float* fp   = (const float*)d_in[1];
    const float* W    = (const float*)d_in[2];
    const float* bias = (const float*)d_in[3];
    float*       out  = (float*)d_out;

    static int smem_set = 0;
    if (!smem_set) {
        cudaFuncSetAttribute(gather_tma_kernel,
                             cudaFuncAttributeMaxDynamicSharedMemorySize,
                             TILE_BYTES);
        smem_set = 1;
    }

    compute_P_kernel<<<80, 256>>>(fp, W, bias);

    dim3 grid(SEQ / CHUNK, BATCH);           // (16, 32) = 512 CTAs
    gather_tma_kernel<<<grid, THREADS, TILE_BYTES>>>(idx, out);
}

// round 7
// speedup vs baseline: 1.1441x; 1.1441x over previous
#include <cuda_runtime.h>
#include <stdint.h>

// Shapes (fixed by the problem)
#define BATCH 32
#define SEQ   4096
#define VOCAB 10
#define FEAT  1024
#define DIM   64

#define CHUNK   256
#define THREADS 256
#define NPROD   80                         // producer CTAs (640 warps)
#define NCONS   (BATCH * (SEQ / CHUNK))    // 512 gather CTAs
#define NCTAS   (NPROD + NCONS)            // 592

// Projected table P[d][v] = b[d] + sum_f fp[v][f] * W[d][f], plus sync state
__device__ float    g_P[DIM * VOCAB];
__device__ unsigned g_pdone;               // producers finished
__device__ unsigned g_fin;                 // CTAs finished (for replay reset)

__device__ __forceinline__ unsigned ld_acquire(const unsigned* p) {
    unsigned v;
    asm volatile("ld.acquire.gpu.global.u32 %0, [%1];" : "=r"(v) : "l"(p));
    return v;
}

// ---------------------------------------------------------------------------
// One fused kernel.
//   CTAs [0, 80):    compute P (one warp per (d,v) pair), then release.
//   CTAs [80, 592):  prefetch indices, wait for P, gather + store.
// All 592 CTAs are wave-1 resident (256 thr, ~3KB smem) -> spin is safe.
// Last CTA resets the counters so every graph replay starts clean.
// ---------------------------------------------------------------------------
__global__ void __launch_bounds__(THREADS)
fused_kernel(const int* __restrict__ idx,
             const float* __restrict__ fp,
             const float* __restrict__ W,
             const float* __restrict__ bias,
             float* __restrict__ out) {
    const int tid = threadIdx.x;
    const int bid = blockIdx.x;

    if (bid < NPROD) {
        // ----- producer: tiny 10x64x1024 GEMM, one warp per (d,v) -----
        const int w    = bid * (THREADS / 32) + (tid >> 5);   // 0..639
        const int lane = tid & 31;
        const int d = w / VOCAB;
        const int v = w - d * VOCAB;

        const float4* fr = reinterpret_cast<const float4*>(fp + v * FEAT);
        const float4* wr = reinterpret_cast<const float4*>(W  + d * FEAT);

        float s = 0.f;
#pragma unroll
        for (int f = lane; f < FEAT / 4; f += 32) {
            float4 a = fr[f];
            float4 c = wr[f];
            s += a.x * c.x + a.y * c.y + a.z * c.z + a.w * c.w;
        }
#pragma unroll
        for (int o = 16; o > 0; o >>= 1)
            s += __shfl_down_sync(0xffffffffu, s, o);

        if (lane == 0)
            g_P[d * VOCAB + v] = s + bias[d];

        __syncthreads();
        __threadfence();                      // publish g_P
        if (tid == 0) atomicAdd(&g_pdone, 1u);
    } else {
        // ----- consumer: gather one (b, 256-token) chunk -----
        __shared__ float sP[DIM * VOCAB];

        const int cid = bid - NPROD;          // 0..511
        const int b   = cid >> 4;             // 16 chunks per batch row
        const int l0  = (cid & 15) * CHUNK;
        const int lq  = tid & 63;             // float4 slot (fixed per thread)
        const int db  = tid >> 6;             // base d-row (0..3)

        // Prefetch this thread's 4 indices BEFORE waiting on P
        int4 iv = *reinterpret_cast<const int4*>(idx + b * SEQ + l0 + lq * 4);

        // Wait for all producers
        if (tid == 0) {
            while (ld_acquire(&g_pdone) < NPROD) __nanosleep(32);
        }
        __syncthreads();

        // Table into shared: [d][v], warp reads <=10 consecutive words later
        for (int i = tid; i < DIM * VOCAB; i += THREADS)
            sP[i] = g_P[i];
        __syncthreads();

        float* ob = out + (b * DIM) * SEQ + l0 + lq * 4;
#pragma unroll
        for (int k = 0; k < 16; k++) {
            const int d = db + 4 * k;
            const float* p = &sP[d * VOCAB];
            float4 r;
            r.x = p[iv.x];
            r.y = p[iv.y];
            r.z = p[iv.z];
            r.w = p[iv.w];
            *reinterpret_cast<float4*>(ob + d * SEQ) = r;
        }
    }

    // ----- replay reset: last CTA to finish zeroes the counters -----
    __syncthreads();
    if (tid == 0) {
        unsigned done = atomicAdd(&g_fin, 1u);
        if (done == NCTAS - 1) {
            atomicExch(&g_pdone, 0u);
            atomicExch(&g_fin, 0u);
        }
    }
}

// ---------------------------------------------------------------------------
// Inputs per metadata order: indices (int32), fp_table (f32), W (f32), b (f32)
// ---------------------------------------------------------------------------
extern "C" void kernel_launch(void* const* d_in, const int* in_sizes, int n_in,
                              void* d_out, int out_size) {
    const int*   idx  = (const int*)d_in[0];
    const float* fp   = (const float*)d_in[1];
    const float* W    = (const float*)d_in[2];
    const float* bias = (const float*)d_in[3];
    float*       out  = (float*)d_out;

    fused_kernel<<<NCTAS, THREADS>>>(idx, fp, W, bias, out);
}

// round 8
// speedup vs baseline: 1.2932x; 1.1303x over previous
#include <cuda_runtime.h>
#include <stdint.h>

// Shapes (fixed by the problem)
#define BATCH 32
#define SEQ   4096
#define VOCAB 10
#define FEAT  1024
#define DIM   64

#define CHUNK   256
#define THREADS 256

// Precomputed projected table: P[d][v] = b[d] + sum_f fp[v][f] * W[d][f]
__device__ float g_P[DIM * VOCAB];

// ---------------------------------------------------------------------------
// Kernel 1: tiny 10x64x1024 GEMM. One warp per (d, v) pair -> 640 warps.
// Signals PDL completion as soon as g_P is published.
// ---------------------------------------------------------------------------
__global__ void compute_P_kernel(const float* __restrict__ fp,
                                 const float* __restrict__ W,
                                 const float* __restrict__ bias) {
    int w    = (blockIdx.x * blockDim.x + threadIdx.x) >> 5;
    int lane = threadIdx.x & 31;
    int d = w / VOCAB;
    int v = w - d * VOCAB;

    const float4* fr = reinterpret_cast<const float4*>(fp + v * FEAT);
    const float4* wr = reinterpret_cast<const float4*>(W  + d * FEAT);

    float s = 0.f;
#pragma unroll
    for (int f = lane; f < FEAT / 4; f += 32) {
        float4 a = fr[f];
        float4 c = wr[f];
        s += a.x * c.x + a.y * c.y + a.z * c.z + a.w * c.w;
    }

#pragma unroll
    for (int o = 16; o > 0; o >>= 1)
        s += __shfl_down_sync(0xffffffffu, s, o);

    if (lane == 0)
        g_P[d * VOCAB + v] = s + bias[d];

    __threadfence();
    // Release the dependent (gather) grid now that this CTA's P is visible.
    cudaTriggerProgrammaticLaunchCompletion();
}

// ---------------------------------------------------------------------------
// Kernel 2: gather. out[(b*DIM + d)*SEQ + l] = P[d][idx[b][l]]
// Launched with PDL: comes up concurrently with kernel 1, does its
// P-independent prelude (index loads), then HW-waits on the grid dependency
// before reading g_P. Store loop identical to the proven R3/R5 version.
// ---------------------------------------------------------------------------
__global__ void __launch_bounds__(THREADS)
gather_kernel(const int* __restrict__ idx, float* __restrict__ out) {
    __shared__ float sP[DIM * VOCAB];

    const int b   = blockIdx.y;
    const int l0  = blockIdx.x * CHUNK;
    const int tid = threadIdx.x;
    const int lq  = tid & 63;            // float4 slot within chunk (fixed)
    const int db  = tid >> 6;            // base d-row (0..3)

    // P-independent prelude: this thread's 4 vocab indices (coalesced 16B)
    int4 iv = *reinterpret_cast<const int4*>(idx + b * SEQ + l0 + lq * 4);

    // HW wait for compute_P_kernel's trigger (no spin, no issue burn)
    cudaGridDependencySynchronize();

    // Projected table into shared: [d][v]
    for (int i = tid; i < DIM * VOCAB; i += THREADS)
        sP[i] = g_P[i];
    __syncthreads();

    float* ob = out + (b * DIM) * SEQ + l0 + lq * 4;

#pragma unroll
    for (int k = 0; k < 16; k++) {
        const int d = db + 4 * k;
        const float* p = &sP[d * VOCAB];
        float4 r;
        r.x = p[iv.x];
        r.y = p[iv.y];
        r.z = p[iv.z];
        r.w = p[iv.w];
        *reinterpret_cast<float4*>(ob + d * SEQ) = r;
    }
}

// ---------------------------------------------------------------------------
// Inputs per metadata order: indices (int32), fp_table (f32), W (f32), b (f32)
// ---------------------------------------------------------------------------
extern "C" void kernel_launch(void* const* d_in, const int* in_sizes, int n_in,
                              void* d_out, int out_size) {
    const int*   idx  = (const int*)d_in[0];
    const float* fp   = (const float*)d_in[1];
    const float* W    = (const float*)d_in[2];
    const float* bias = (const float*)d_in[3];
    float*       out  = (float*)d_out;

    // Producer: 640 warps -> 80 blocks of 256 threads
    compute_P_kernel<<<80, 256>>>(fp, W, bias);

    // Consumer: PDL launch — overlaps grid bring-up + prelude with kernel 1
    cudaLaunchConfig_t cfg = {};
    cfg.gridDim        = dim3(SEQ / CHUNK, BATCH);   // (16, 32) = 512 CTAs
    cfg.blockDim       = dim3(THREADS, 1, 1);
    cfg.dynamicSmemBytes = 0;
    cfg.stream         = 0;                          // same stream as k1

    cudaLaunchAttribute attr[1];
    attr[0].id = cudaLaunchAttributeProgrammaticStreamSerialization;
    attr[0].val.programmaticStreamSerializationAllowed = 1;
    cfg.attrs    = attr;
    cfg.numAttrs = 1;

    cudaLaunchKernelEx(&cfg, gather_kernel, idx, out);
}